// round 3
// baseline (speedup 1.0000x reference)
#include <cuda_runtime.h>

#define WID 512
#define HEI 512
#define NPIX (WID*HEI)
#define RAD 10
#define KS 21
#define HT 128            // horizontal tile width
#define HSH (HT + 2*RAD)  // 148
#define VR 4              // output rows per thread in vertical pass

// ---------------- static device scratch ----------------
__device__ float g_wG[KS], g_wD[KS];
__device__ float g_hsG[WID], g_hsD[WID];
__device__ float g_SDinv;

__device__ float  g_gray[NPIX];
__device__ float  g_meanI[NPIX];
__device__ float  g_invvar[NPIX];
__device__ float  g_bnorm[NPIX];
__device__ float  g_s1[NPIX], g_s2[NPIX];
__device__ float  g_a1[NPIX], g_b1[NPIX];
__device__ float4 g_Q[NPIX];
__device__ float4 g_t1[NPIX], g_t2[NPIX], g_t3[NPIX];
__device__ float4 g_a[NPIX], g_b[NPIX], g_sp[NPIX];

// ---------------- helpers ----------------
__device__ __forceinline__ void fma4(float4& acc, float w, const float4& v) {
    acc.x = fmaf(w, v.x, acc.x);
    acc.y = fmaf(w, v.y, acc.y);
    acc.z = fmaf(w, v.z, acc.z);
    acc.w = fmaf(w, v.w, acc.w);
}

__device__ __forceinline__ float4 zero4() { return make_float4(0.f, 0.f, 0.f, 0.f); }

__device__ __forceinline__ float4 softmax4(float4 z) {
    float m = fmaxf(fmaxf(z.x, z.y), fmaxf(z.z, z.w));
    float ex = __expf(z.x - m);
    float ey = __expf(z.y - m);
    float ez = __expf(z.z - m);
    float ew = __expf(z.w - m);
    float inv = 1.f / (ex + ey + ez + ew);
    return make_float4(ex * inv, ey * inv, ez * inv, ew * inv);
}

// ---------------- init: weights + 1D border sums ----------------
__global__ void k_init() {
    __shared__ float swG[KS], swD[KS];
    int t = threadIdx.x;
    if (t < KS) {
        float d = (float)(t - RAD);
        float wg = expf(-(d * d) / (2.0f * 2.5f * 2.5f));
        float th = 10.0f / 3.0f;
        float wd = expf(-(d * d) / (2.0f * th * th));
        swG[t] = wg; swD[t] = wd;
        g_wG[t] = wg; g_wD[t] = wd;
    }
    __syncthreads();
    int x = t;
    if (x < WID) {
        float sg = 0.f, sd = 0.f;
        for (int k = 0; k < KS; k++) {
            int xx = x + k - RAD;
            if (xx >= 0 && xx < WID) { sg += swG[k]; sd += swD[k]; }
        }
        g_hsG[x] = sg; g_hsD[x] = sd;
    }
    if (t == 0) {
        float s = 0.f;
        for (int k = 0; k < KS; k++) s += swD[k];
        g_SDinv = 1.0f / (s * s);
    }
}

// ---------------- grayscale ----------------
__global__ void k_gray(const float* __restrict__ img) {
    int i = blockIdx.x * blockDim.x + threadIdx.x;
    if (i >= NPIX) return;
    g_gray[i] = 0.2989f * img[3 * i] + 0.5870f * img[3 * i + 1] + 0.1140f * img[3 * i + 2];
}

// ---------------- Q0 = softmax(-unary) ----------------
__global__ void k_softmax0(const float4* __restrict__ unary) {
    int i = blockIdx.x * blockDim.x + threadIdx.x;
    if (i >= NPIX) return;
    float4 u = unary[i];
    g_Q[i] = softmax4(make_float4(-u.x, -u.y, -u.z, -u.w));
}

// ---------------- scalar horizontal pass (guided weights) ----------------
// MODE 0: in = gray, gray^2 -> s1, s2
// MODE 1: in = a1, b1      -> s1, s2
template <int MODE>
__global__ void __launch_bounds__(HT) k_hscalar() {
    __shared__ float s1[HSH], s2[HSH];
    int y = blockIdx.y, x0 = blockIdx.x * HT, i = threadIdx.x;
    float wd[KS];
#pragma unroll
    for (int t = 0; t < KS; t++) wd[t] = g_wD[t];
    for (int s = i; s < HSH; s += HT) {
        int x = x0 + s - RAD;
        float a = 0.f, b = 0.f;
        if (x >= 0 && x < WID) {
            int p = y * WID + x;
            if (MODE == 0) { a = g_gray[p]; b = a * a; }
            else           { a = g_a1[p];  b = g_b1[p]; }
        }
        s1[s] = a; s2[s] = b;
    }
    __syncthreads();
    float A = 0.f, B = 0.f;
#pragma unroll
    for (int t = 0; t < KS; t++) {
        A = fmaf(wd[t], s1[i + t], A);
        B = fmaf(wd[t], s2[i + t], B);
    }
    int o = y * WID + x0 + i;
    g_s1[o] = A; g_s2[o] = B;
}

// ---------------- scalar vertical pass 1: meanI / invvar / a1 / b1 ----------------
__global__ void __launch_bounds__(128) k_vpre1() {
    int x = blockIdx.x * 128 + threadIdx.x;
    int y0 = blockIdx.y * VR;
    float wd[KS];
#pragma unroll
    for (int t = 0; t < KS; t++) wd[t] = g_wD[t];
    float A1[VR], A2[VR];
#pragma unroll
    for (int r = 0; r < VR; r++) { A1[r] = 0.f; A2[r] = 0.f; }
#pragma unroll
    for (int j = 0; j < KS + VR - 1; j++) {
        int row = y0 + j - RAD;
        float v1 = 0.f, v2 = 0.f;
        if (row >= 0 && row < HEI) { int p = row * WID + x; v1 = g_s1[p]; v2 = g_s2[p]; }
#pragma unroll
        for (int r = 0; r < VR; r++) {
            int t = j - r;
            if (t >= 0 && t < KS) {
                A1[r] = fmaf(wd[t], v1, A1[r]);
                A2[r] = fmaf(wd[t], v2, A2[r]);
            }
        }
    }
    float SDinv = g_SDinv;
    float hx = g_hsD[x];
#pragma unroll
    for (int r = 0; r < VR; r++) {
        int y = y0 + r, idx = y * WID + x;
        float g = g_gray[idx];
        float mI  = (A1[r] - g) * SDinv;
        float mII = (A2[r] - g * g) * SDinv;
        float mp1 = (hx * g_hsD[y] - 1.f) * SDinv;
        float var = mII - mI * mI;
        float iv  = 1.f / (var + 1e-4f);
        float a1  = mI * (1.f - mp1) * iv;
        float b1  = mp1 - a1 * mI;
        g_meanI[idx] = mI; g_invvar[idx] = iv; g_a1[idx] = a1; g_b1[idx] = b1;
    }
}

// ---------------- scalar vertical pass 2: bilateral norm ----------------
__global__ void __launch_bounds__(128) k_vpre2() {
    int x = blockIdx.x * 128 + threadIdx.x;
    int y0 = blockIdx.y * VR;
    float wd[KS];
#pragma unroll
    for (int t = 0; t < KS; t++) wd[t] = g_wD[t];
    float A1[VR], A2[VR];
#pragma unroll
    for (int r = 0; r < VR; r++) { A1[r] = 0.f; A2[r] = 0.f; }
#pragma unroll
    for (int j = 0; j < KS + VR - 1; j++) {
        int row = y0 + j - RAD;
        float v1 = 0.f, v2 = 0.f;
        if (row >= 0 && row < HEI) { int p = row * WID + x; v1 = g_s1[p]; v2 = g_s2[p]; }
#pragma unroll
        for (int r = 0; r < VR; r++) {
            int t = j - r;
            if (t >= 0 && t < KS) {
                A1[r] = fmaf(wd[t], v1, A1[r]);
                A2[r] = fmaf(wd[t], v2, A2[r]);
            }
        }
    }
    float SDinv = g_SDinv;
#pragma unroll
    for (int r = 0; r < VR; r++) {
        int idx = (y0 + r) * WID + x;
        float g = g_gray[idx];
        float gfa = (A1[r] - g_a1[idx]) * SDinv;
        float gfb = (A2[r] - g_b1[idx]) * SDinv;
        g_bnorm[idx] = gfa * g + gfb;
    }
}

// ---------------- iteration: H pass of Q (3 outputs) ----------------
__global__ void __launch_bounds__(HT) k_hiter() {
    __shared__ float4 sQ[HSH], sGQ[HSH];
    int y = blockIdx.y, x0 = blockIdx.x * HT, i = threadIdx.x;
    float wg[KS], wd[KS];
#pragma unroll
    for (int t = 0; t < KS; t++) { wg[t] = g_wG[t]; wd[t] = g_wD[t]; }
    for (int s = i; s < HSH; s += HT) {
        int x = x0 + s - RAD;
        float4 q = zero4(); float g = 0.f;
        if (x >= 0 && x < WID) { int p = y * WID + x; q = g_Q[p]; g = g_gray[p]; }
        sQ[s] = q;
        sGQ[s] = make_float4(q.x * g, q.y * g, q.z * g, q.w * g);
    }
    __syncthreads();
    float4 aG = zero4(), aD = zero4(), aI = zero4();
#pragma unroll
    for (int t = 0; t < KS; t++) {
        float4 q = sQ[i + t], gq = sGQ[i + t];
        fma4(aG, wg[t], q);
        fma4(aD, wd[t], q);
        fma4(aI, wd[t], gq);
    }
    int o = y * WID + x0 + i;
    g_t1[o] = aG; g_t2[o] = aD; g_t3[o] = aI;
}

// ---------------- iteration: V pass + a/b/spatial elementwise ----------------
__global__ void __launch_bounds__(128) k_viter() {
    int x = blockIdx.x * 128 + threadIdx.x;
    int y0 = blockIdx.y * VR;
    float wg[KS], wd[KS];
#pragma unroll
    for (int t = 0; t < KS; t++) { wg[t] = g_wG[t]; wd[t] = g_wD[t]; }
    float4 AG[VR], AD[VR], AI[VR];
#pragma unroll
    for (int r = 0; r < VR; r++) { AG[r] = zero4(); AD[r] = zero4(); AI[r] = zero4(); }
#pragma unroll
    for (int j = 0; j < KS + VR - 1; j++) {
        int row = y0 + j - RAD;
        float4 v1 = zero4(), v2 = zero4(), v3 = zero4();
        if (row >= 0 && row < HEI) {
            int p = row * WID + x;
            v1 = g_t1[p]; v2 = g_t2[p]; v3 = g_t3[p];
        }
#pragma unroll
        for (int r = 0; r < VR; r++) {
            int t = j - r;
            if (t >= 0 && t < KS) {
                fma4(AG[r], wg[t], v1);
                fma4(AD[r], wd[t], v2);
                fma4(AI[r], wd[t], v3);
            }
        }
    }
    float SDinv = g_SDinv;
    float hgx = g_hsG[x];
#pragma unroll
    for (int r = 0; r < VR; r++) {
        int y = y0 + r, idx = y * WID + x;
        float4 q = g_Q[idx];
        float g = g_gray[idx], mI = g_meanI[idx], iv = g_invvar[idx];
        // spatial message: 3 * gauss(Q)/spatial_norm ; S_G cancels
        float spc = 3.f / (hgx * g_hsG[y] - 1.f);
        float4 sp = make_float4((AG[r].x - q.x) * spc, (AG[r].y - q.y) * spc,
                                (AG[r].z - q.z) * spc, (AG[r].w - q.w) * spc);
        // guided filter intermediates
        float4 mp  = make_float4((AD[r].x - q.x) * SDinv, (AD[r].y - q.y) * SDinv,
                                 (AD[r].z - q.z) * SDinv, (AD[r].w - q.w) * SDinv);
        float4 mIp = make_float4((AI[r].x - g * q.x) * SDinv, (AI[r].y - g * q.y) * SDinv,
                                 (AI[r].z - g * q.z) * SDinv, (AI[r].w - g * q.w) * SDinv);
        float4 a = make_float4((mIp.x - mI * mp.x) * iv, (mIp.y - mI * mp.y) * iv,
                               (mIp.z - mI * mp.z) * iv, (mIp.w - mI * mp.w) * iv);
        float4 b = make_float4(mp.x - a.x * mI, mp.y - a.y * mI,
                               mp.z - a.z * mI, mp.w - a.w * mI);
        g_a[idx] = a; g_b[idx] = b; g_sp[idx] = sp;
    }
}

// ---------------- iteration: H pass of a, b ----------------
__global__ void __launch_bounds__(HT) k_hab() {
    __shared__ float4 sA[HSH], sB[HSH];
    int y = blockIdx.y, x0 = blockIdx.x * HT, i = threadIdx.x;
    float wd[KS];
#pragma unroll
    for (int t = 0; t < KS; t++) wd[t] = g_wD[t];
    for (int s = i; s < HSH; s += HT) {
        int x = x0 + s - RAD;
        float4 a = zero4(), b = zero4();
        if (x >= 0 && x < WID) { int p = y * WID + x; a = g_a[p]; b = g_b[p]; }
        sA[s] = a; sB[s] = b;
    }
    __syncthreads();
    float4 AA = zero4(), AB = zero4();
#pragma unroll
    for (int t = 0; t < KS; t++) {
        fma4(AA, wd[t], sA[i + t]);
        fma4(AB, wd[t], sB[i + t]);
    }
    int o = y * WID + x0 + i;
    g_t1[o] = AA; g_t2[o] = AB;
}

// ---------------- iteration: V pass of a,b + message + softmax ----------------
template <bool FINAL>
__global__ void __launch_bounds__(128) k_vfin(const float4* __restrict__ unary,
                                              float4* __restrict__ dout) {
    int x = blockIdx.x * 128 + threadIdx.x;
    int y0 = blockIdx.y * VR;
    float wd[KS];
#pragma unroll
    for (int t = 0; t < KS; t++) wd[t] = g_wD[t];
    float4 AA[VR], AB[VR];
#pragma unroll
    for (int r = 0; r < VR; r++) { AA[r] = zero4(); AB[r] = zero4(); }
#pragma unroll
    for (int j = 0; j < KS + VR - 1; j++) {
        int row = y0 + j - RAD;
        float4 v1 = zero4(), v2 = zero4();
        if (row >= 0 && row < HEI) { int p = row * WID + x; v1 = g_t1[p]; v2 = g_t2[p]; }
#pragma unroll
        for (int r = 0; r < VR; r++) {
            int t = j - r;
            if (t >= 0 && t < KS) {
                fma4(AA[r], wd[t], v1);
                fma4(AB[r], wd[t], v2);
            }
        }
    }
    float SDinv = g_SDinv;
#pragma unroll
    for (int r = 0; r < VR; r++) {
        int idx = (y0 + r) * WID + x;
        float g = g_gray[idx];
        float ibn = 10.f / g_bnorm[idx];   // fold the bilateral compat weight (10) in
        float4 av = g_a[idx], bv = g_b[idx], sp = g_sp[idx], u = unary[idx];
        float4 z;
        {
            float gfa = (AA[r].x - av.x) * SDinv, gfb = (AB[r].x - bv.x) * SDinv;
            z.x = sp.x + (gfa * g + gfb) * ibn - u.x;
        }
        {
            float gfa = (AA[r].y - av.y) * SDinv, gfb = (AB[r].y - bv.y) * SDinv;
            z.y = sp.y + (gfa * g + gfb) * ibn - u.y;
        }
        {
            float gfa = (AA[r].z - av.z) * SDinv, gfb = (AB[r].z - bv.z) * SDinv;
            z.z = sp.z + (gfa * g + gfb) * ibn - u.z;
        }
        {
            float gfa = (AA[r].w - av.w) * SDinv, gfb = (AB[r].w - bv.w) * SDinv;
            z.w = sp.w + (gfa * g + gfb) * ibn - u.w;
        }
        float4 qn = softmax4(z);
        if (FINAL) dout[idx] = qn; else g_Q[idx] = qn;
    }
}

// ---------------- launch ----------------
extern "C" void kernel_launch(void* const* d_in, const int* in_sizes, int n_in,
                              void* d_out, int out_size) {
    const float* unary = nullptr;
    const float* image = nullptr;
    for (int i = 0; i < n_in; i++) {
        if (in_sizes[i] == NPIX * 4) unary = (const float*)d_in[i];
        else if (in_sizes[i] == NPIX * 3) image = (const float*)d_in[i];
    }

    dim3 bh(HT), gh(WID / HT, HEI);       // horizontal passes: 4 x 512 blocks of 128
    dim3 bv(128), gv(WID / 128, HEI / VR); // vertical passes: 4 x 128 blocks of 128

    k_init<<<1, 512>>>();
    k_gray<<<NPIX / 256, 256>>>(image);
    k_softmax0<<<NPIX / 256, 256>>>((const float4*)unary);

    // image-only precompute (mean_I, inv_var, bilateral norm)
    k_hscalar<0><<<gh, bh>>>();
    k_vpre1<<<gv, bv>>>();
    k_hscalar<1><<<gh, bh>>>();
    k_vpre2<<<gv, bv>>>();

    // 5 mean-field iterations
    for (int it = 0; it < 5; it++) {
        k_hiter<<<gh, bh>>>();
        k_viter<<<gv, bv>>>();
        k_hab<<<gh, bh>>>();
        if (it < 4) k_vfin<false><<<gv, bv>>>((const float4*)unary, nullptr);
        else        k_vfin<true><<<gv, bv>>>((const float4*)unary, (float4*)d_out);
    }
}